// round 15
// baseline (speedup 1.0000x reference)
#include <cuda_runtime.h>
#include <cuda_bf16.h>
#include <cstdint>
#include <stdint.h>

// ---------------- problem constants -----------------------------------------
#define NL   1024
#define NC   512
#define NCOL 1728
#define NCOLP 1792
#define NM   2048
#define NBH  16
#define GK   1536        // logical split-concat K' = 3*512
#define GKS  1024        // physical storage: [hi(512) | lo(512)]

// ---------------- scratch ----------------------------------------------------
__device__ float g_Kp[NBH * NL * 12];
__device__ float g_kb[NBH * NL];
__device__ float g_bias[NCOL];
__device__ __nv_bfloat16 g_xc[NM * GKS];         // LN(x) [hi|lo]
__device__ __nv_bfloat16 g_Wc[NCOLP * GKS];      // packed W^T [hi|lo]
__device__ __nv_bfloat16 g_Oc[NM * GKS];         // attn out [hi|lo]
__device__ __nv_bfloat16 g_WoC[NC * GKS];        // wo^T [hi|lo]
__device__ __nv_bfloat16 g_Qc[NBH * NL * 160];   // q_ext bf16 [hi|lo]; pads stay 0
__device__ __nv_bfloat16 g_Kc[NBH * NL * 160];
__device__ __nv_bfloat16 g_VhT[NBH * 64 * NL];   // V hi, transposed [bh*64+d][l]
__device__ __nv_bfloat16 g_VlT[NBH * 64 * NL];   // V lo, transposed

__device__ __forceinline__ void bf16split(float v, __nv_bfloat16& hi, __nv_bfloat16& lo) {
    hi = __float2bfloat16(v);
    lo = __float2bfloat16(v - __bfloat162float(hi));
}
__device__ __forceinline__ uint32_t pk2(__nv_bfloat16 a, __nv_bfloat16 b) {
    return (uint32_t)__bfloat16_as_ushort(a) | ((uint32_t)__bfloat16_as_ushort(b) << 16);
}
__device__ __forceinline__ uint32_t smem_u32(const void* p) {
    uint32_t a;
    asm("{ .reg .u64 t; cvta.to.shared.u64 t, %1; cvt.u32.u64 %0, t; }" : "=r"(a) : "l"(p));
    return a;
}
__device__ __forceinline__ void mma16816(float* c, const uint32_t* a, const uint32_t* b) {
    asm volatile("mma.sync.aligned.m16n8k16.row.col.f32.bf16.bf16.f32 "
                 "{%0,%1,%2,%3}, {%4,%5,%6,%7}, {%8,%9}, {%0,%1,%2,%3};"
                 : "+f"(c[0]), "+f"(c[1]), "+f"(c[2]), "+f"(c[3])
                 : "r"(a[0]), "r"(a[1]), "r"(a[2]), "r"(a[3]), "r"(b[0]), "r"(b[1]));
}
__device__ __forceinline__ void cpa16(uint32_t dst, const void* src) {
    asm volatile("cp.async.ca.shared.global [%0], [%1], 16;" :: "r"(dst), "l"(src));
}
#define CP_COMMIT() asm volatile("cp.async.commit_group;")
#define CP_WAIT0()  asm volatile("cp.async.wait_group 0;")
#define LDMX4(r0, r1, r2, r3, addr)                                                   \
    asm volatile("ldmatrix.sync.aligned.m8n8.x4.shared.b16 {%0,%1,%2,%3}, [%4];"      \
                 : "=r"(r0), "=r"(r1), "=r"(r2), "=r"(r3) : "r"(addr))

// ---------------- 1) pack weights via 32x32 smem transpose -------------------
__global__ void __launch_bounds__(256) pack_w(const float* __restrict__ wq,
                                              const float* __restrict__ wk,
                                              const float* __restrict__ wv,
                                              const float* __restrict__ wqp,
                                              const float* __restrict__ wkp,
                                              const float* __restrict__ wo,
                                              const float* __restrict__ pscale) {
    __shared__ float smt[32][33];
    int tx = threadIdx.x & 31, ty = threadIdx.x >> 5;
    int k0 = blockIdx.x * 32;
    int nt = blockIdx.y;
    if (nt < 56) {
        int n0 = nt * 32;
        const float* src; int ld, col;
        if (n0 < 512)       { src = wq;  ld = 512; col = n0; }
        else if (n0 < 1024) { src = wk;  ld = 512; col = n0 - 512; }
        else if (n0 < 1536) { src = wv;  ld = 512; col = n0 - 1024; }
        else if (n0 < 1632) { src = wqp; ld = 96;  col = n0 - 1536; }
        else if (n0 < 1728) { src = wkp; ld = 96;  col = n0 - 1632; }
        else                { src = nullptr; ld = 0; col = 0; }
#pragma unroll
        for (int i = 0; i < 4; i++) {
            int kr = ty + i * 8;
            smt[kr][tx] = src ? src[(size_t)(k0 + kr) * ld + col + tx] : 0.f;
        }
        __syncthreads();
#pragma unroll
        for (int i = 0; i < 4; i++) {
            int n = n0 + ty + i * 8, k = k0 + tx;
            float v = smt[tx][ty + i * 8];
            if (n < 512) v *= 0.125f;
            else if (n >= 1536 && n < 1632) v *= 2.0f * pscale[(n - 1536) / 12];
            __nv_bfloat16 hi, lo; bf16split(v, hi, lo);
            g_Wc[(size_t)n * GKS + k]       = hi;
            g_Wc[(size_t)n * GKS + 512 + k] = lo;
        }
    } else {
        int n0 = (nt - 56) * 32;
#pragma unroll
        for (int i = 0; i < 4; i++) {
            int kr = ty + i * 8;
            smt[kr][tx] = wo[(size_t)(k0 + kr) * 512 + n0 + tx];
        }
        __syncthreads();
#pragma unroll
        for (int i = 0; i < 4; i++) {
            int n = n0 + ty + i * 8, k = k0 + tx;
            __nv_bfloat16 hi, lo; bf16split(smt[tx][ty + i * 8], hi, lo);
            g_WoC[(size_t)n * GKS + k]       = hi;
            g_WoC[(size_t)n * GKS + 512 + k] = lo;
        }
    }
}

__global__ void pack_bias(const float* __restrict__ bq, const float* __restrict__ bk,
                          const float* __restrict__ bv, const float* __restrict__ bqp,
                          const float* __restrict__ bkp, const float* __restrict__ pscale) {
    int n = blockIdx.x * 256 + threadIdx.x;
    if (n >= NCOL) return;
    float bb;
    if (n < 512)        bb = bq[n] * 0.125f;
    else if (n < 1024)  bb = bk[n - 512];
    else if (n < 1536)  bb = bv[n - 1024];
    else if (n < 1632) { int c = n - 1536; bb = bqp[c] * 2.0f * pscale[c / 12]; }
    else               { int c = n - 1632; bb = bkp[c]; }
    g_bias[n] = bb;
}

// ---------------- 2) LayerNorm -> [hi|lo] bf16 -------------------------------
__global__ void ln_kernel(const float* __restrict__ f, const float* __restrict__ g,
                          const float* __restrict__ bb) {
    int row = blockIdx.x, t = threadIdx.x;
    const float* xr = f + (size_t)row * NC;
    float v0 = xr[t], v1 = xr[t + 256];
    float s = v0 + v1, s2 = v0 * v0 + v1 * v1;
#pragma unroll
    for (int o = 16; o > 0; o >>= 1) {
        s  += __shfl_xor_sync(0xffffffffu, s, o);
        s2 += __shfl_xor_sync(0xffffffffu, s2, o);
    }
    __shared__ float sh[16];
    if ((t & 31) == 0) { sh[t >> 5] = s; sh[8 + (t >> 5)] = s2; }
    __syncthreads();
    float ts = 0.f, ts2 = 0.f;
#pragma unroll
    for (int i = 0; i < 8; i++) { ts += sh[i]; ts2 += sh[8 + i]; }
    float mu   = ts * (1.0f / NC);
    float var  = ts2 * (1.0f / NC) - mu * mu;
    float rstd = rsqrtf(var + 1e-5f);
    float x0 = (v0 - mu) * rstd * g[t] + bb[t];
    float x1 = (v1 - mu) * rstd * g[t + 256] + bb[t + 256];
    size_t base = (size_t)row * GKS;
    __nv_bfloat16 h0, l0, h1, l1;
    bf16split(x0, h0, l0); bf16split(x1, h1, l1);
    g_xc[base + t]       = h0;  g_xc[base + t + 256]       = h1;
    g_xc[base + 512 + t] = l0;  g_xc[base + 512 + t + 256] = l1;
}

// ---------------- 3) GEMM: ldmatrix + BK=128, 2-stage, interleaved cp.async --
// Logical K'=1536 over 2-plane storage:
//   A plane map (x/O = [hi,lo,hi]):  ka = k0>=1024 ? k0-1024 : k0
//   B plane map (W   = [hi,hi,lo]):  kb = k0>=512  ? k0-512  : k0
template <int MODE, int MT, int NT>
__global__ void __launch_bounds__(256) gemm_cp(const float* __restrict__ bias2,
                                               float* __restrict__ outp) {
    constexpr int STAGE = (MT + NT) * 272;
    constexpr int MFRAG = MT / 32;
    constexpr int NWN   = NT / 4;
    constexpr int NFRAG = NWN / 8;
    constexpr int NFP   = NWN / 16;
    constexpr int ITERS = (MT + NT) * 16 / 256;
    extern __shared__ char gsm[];
    uint32_t smBase = smem_u32(gsm);
    int tid = threadIdx.x, lane = tid & 31, wid = tid >> 5;
    int wm = wid & 1, wn = wid >> 1;
    int l16 = lane & 15, lh = lane >> 4;
    int m0 = blockIdx.y * MT, n0 = blockIdx.x * NT;
    const __nv_bfloat16* Ap = (MODE == 0 ? g_xc : g_Oc) + (size_t)m0 * GKS;
    const __nv_bfloat16* Bp = (MODE == 0 ? g_Wc : g_WoC) + (size_t)n0 * GKS;

    int row_c = tid >> 4, ch_c = tid & 15;   // chunk geometry per thread

#define GEMM_CHUNK(S, I) do {                                                      \
    int st_ = (S) & 1; int k0_ = (S) * 128;                                        \
    int ka_ = (k0_ >= 1024) ? (k0_ - 1024) : k0_;                                  \
    int kb_ = (k0_ >= 512)  ? (k0_ - 512)  : k0_;                                  \
    int row_ = row_c + (I) * 16;                                                   \
    const __nv_bfloat16* src_ = (row_ < MT)                                        \
        ? Ap + (size_t)row_ * GKS + ka_ + ch_c * 8                                 \
        : Bp + (size_t)(row_ - MT) * GKS + kb_ + ch_c * 8;                         \
    cpa16(smBase + st_ * STAGE + row_ * 272 + ch_c * 16, src_);                    \
} while (0)

    // prologue: full stage 0
#pragma unroll
    for (int i = 0; i < ITERS; i++) GEMM_CHUNK(0, i);
    CP_COMMIT();

    float c[MFRAG][NFRAG][4];
#pragma unroll
    for (int i = 0; i < MFRAG; i++)
#pragma unroll
        for (int j = 0; j < NFRAG; j++)
#pragma unroll
            for (int e = 0; e < 4; e++) c[i][j][e] = 0.f;

    const int NS = GK / 128;   // 12
    for (int s = 0; s < NS; s++) {
        CP_WAIT0();
        __syncthreads();
        bool pf = (s + 1 < NS);
        uint32_t aB = smBase + (s & 1) * STAGE;
        uint32_t a_ad = aB + (wm * (MT / 2) + l16) * 272 + lh * 16;
        uint32_t b_ad = aB + MT * 272 + (wn * NWN + l16) * 272 + lh * 16;
#pragma unroll
        for (int ks = 0; ks < 8; ks++) {
            // interleaved prefetch of next stage: ITERS/8-ish chunks per ks
            if (pf) {
#pragma unroll
                for (int i = (ks * ITERS) / 8; i < ((ks + 1) * ITERS) / 8; i++)
                    GEMM_CHUNK(s + 1, i);
            }
            uint32_t a[MFRAG][4], bb[NFP][4];
#pragma unroll
            for (int mf = 0; mf < MFRAG; mf++)
                LDMX4(a[mf][0], a[mf][1], a[mf][2], a[mf][3], a_ad + mf * 4352 + ks * 32);
#pragma unroll
            for (int nfp = 0; nfp < NFP; nfp++)
                LDMX4(bb[nfp][0], bb[nfp][1], bb[nfp][2], bb[nfp][3], b_ad + nfp * 4352 + ks * 32);
#pragma unroll
            for (int mf = 0; mf < MFRAG; mf++)
#pragma unroll
                for (int nfp = 0; nfp < NFP; nfp++) {
                    uint32_t be[2] = { bb[nfp][0], bb[nfp][2] };
                    uint32_t bo[2] = { bb[nfp][1], bb[nfp][3] };
                    mma16816(c[mf][2 * nfp],     a[mf], be);
                    mma16816(c[mf][2 * nfp + 1], a[mf], bo);
                }
        }
        if (pf) CP_COMMIT();
        __syncthreads();
    }
#undef GEMM_CHUNK

    // epilogue
#pragma unroll
    for (int mf = 0; mf < MFRAG; mf++) {
#pragma unroll
        for (int nf = 0; nf < NFRAG; nf++) {
#pragma unroll
            for (int ep = 0; ep < 2; ep++) {
                int m = m0 + wm * (MT / 2) + mf * 16 + (lane >> 2) + ep * 8;
                int n = n0 + wn * NWN + nf * 8 + (lane & 3) * 2;
                float v0 = c[mf][nf][ep * 2 + 0];
                float v1 = c[mf][nf][ep * 2 + 1];
                if (MODE == 0) {
                    if (n < NCOL) {
                        v0 += g_bias[n]; v1 += g_bias[n + 1];
                        int b = m >> 10, l = m & 1023;
                        __nv_bfloat16 h0, lo0, h1, lo1;
                        bf16split(v0, h0, lo0); bf16split(v1, h1, lo1);
                        if (n < 512) {
                            int h = n >> 6, d = n & 63;
                            size_t row = (size_t)((b * 8 + h) * NL + l) * 160;
                            *(uint32_t*)&g_Qc[row + d]      = pk2(h0, h1);
                            *(uint32_t*)&g_Qc[row + 80 + d] = pk2(lo0, lo1);
                        } else if (n < 1024) {
                            int n2 = n - 512; int h = n2 >> 6, d = n2 & 63;
                            size_t row = (size_t)((b * 8 + h) * NL + l) * 160;
                            *(uint32_t*)&g_Kc[row + d]      = pk2(h0, h1);
                            *(uint32_t*)&g_Kc[row + 80 + d] = pk2(lo0, lo1);
                        } else if (n < 1536) {
                            int n2 = n - 1024; int h = n2 >> 6, d = n2 & 63;
                            size_t vb = (size_t)((b * 8 + h) * 64 + d) * NL + l;
                            g_VhT[vb]      = h0;
                            g_VhT[vb + NL] = h1;
                            g_VlT[vb]      = lo0;
                            g_VlT[vb + NL] = lo1;
                        } else if (n < 1632) {
                            int cc = n - 1536; int h = cc / 12, r = cc - h * 12;
                            size_t row = (size_t)((b * 8 + h) * NL + l) * 160;
                            *(uint32_t*)&g_Qc[row + 64 + r]  = pk2(h0, h1);
                            *(uint32_t*)&g_Qc[row + 144 + r] = pk2(lo0, lo1);
                        } else {
                            int cc = n - 1632; int h = cc / 12, r = cc - h * 12;
                            size_t row = (size_t)((b * 8 + h) * NL + l);
                            *(uint32_t*)&g_Kc[row * 160 + 64 + r]  = pk2(h0, h1);
                            *(uint32_t*)&g_Kc[row * 160 + 144 + r] = pk2(lo0, lo1);
                            *(float2*)&g_Kp[row * 12 + r] = make_float2(v0, v1);
                        }
                    }
                } else {
                    *(float2*)&outp[(size_t)m * NC + n] =
                        make_float2(v0 + bias2[n], v1 + bias2[n + 1]);
                }
            }
        }
    }
}

// ---------------- 4) key bias -----------------------------------------------
__global__ void kbias_kernel(const float* __restrict__ pscale) {
    int row = blockIdx.x * blockDim.x + threadIdx.x;
    if (row >= NBH * NL) return;
    int h = (row >> 10) & 7;
    float s = 0.f;
#pragma unroll
    for (int r = 0; r < 12; r++) { float v = g_Kp[row * 12 + r]; s += v * v; }
    g_kb[row] = -pscale[h] * s;
}

// ---------------- 5) flash attention: S 3-phase, PV 3-phase ------------------
#define FBUF0 21504
#define FBUFSZ 40192
#define FV_OFF 21504
#define FVL_OFF 30720
#define FKB_OFF 39936
#define FLASH_SMEM (21504 + 2 * FBUFSZ)

__global__ void __launch_bounds__(128) flash_tc() {
    extern __shared__ char fsm[];
    __nv_bfloat16* Qs = (__nv_bfloat16*)fsm;
    uint32_t sm = smem_u32(fsm);

    int tid = threadIdx.x, lane = tid & 31, wid = tid >> 5;
    int l16 = lane & 15, lh = lane >> 4;
    int bh = blockIdx.y, i0 = blockIdx.x << 6;

    const __nv_bfloat16* Qg = g_Qc + (size_t)(bh * NL + i0) * 160;
    const __nv_bfloat16* Kg0 = g_Kc + (size_t)(bh * NL) * 160;
    const __nv_bfloat16* VhG = g_VhT + (size_t)(bh * 64) * NL;
    const __nv_bfloat16* VlG = g_VlT + (size_t)(bh * 64) * NL;
    const float* kbG = g_kb + bh * NL;

#define FISSUE(KT) do {                                                              \
    int j0_ = (KT) << 6;                                                             \
    uint32_t bufb_ = sm + FBUF0 + ((KT) & 1) * FBUFSZ;                               \
    const __nv_bfloat16* Kg_ = Kg0 + (size_t)j0_ * 160;                              \
    _Pragma("unroll")                                                                \
    for (int i_ = 0; i_ < 10; i_++) {                                                \
        int idx_ = tid + i_ * 128;                                                   \
        int row_ = idx_ / 20, ch_ = idx_ % 20;                                       \
        cpa16(bufb_ + row_ * 336 + ch_ * 16, Kg_ + row_ * 160 + ch_ * 8);            \
    }                                                                                \
    _Pragma("unroll")                                                                \
    for (int i_ = 0; i_ < 4; i_++) {                                                 \
        int idx_ = tid + i_ * 128;                                                   \
        int d_ = idx_ >> 3, ch_ = idx_ & 7;                                          \
        cpa16(bufb_ + FV_OFF + d_ * 144 + ch_ * 16, VhG + (size_t)d_ * NL + j0_ + ch_ * 8); \
        cpa16(bufb_ + FVL_OFF + d_ * 144 + ch_ * 16, VlG + (size_t)d_ * NL + j0_ + ch_ * 8); \
    }                                                                                \
    if (tid < 16) cpa16(bufb_ + FKB_OFF + tid * 16, kbG + j0_ + tid * 4);            \
    CP_COMMIT();                                                                     \
} while (0)

    FISSUE(0);

    for (int idx = tid; idx < 64 * 20; idx += 128) {
        int row = idx / 20, ch = idx % 20;
        *(uint4*)&Qs[row * 168 + ch * 8] = *(const uint4*)(Qg + row * 160 + ch * 8);
    }
    uint32_t qa_base = sm + (wid * 16 + l16) * 336 + lh * 16;

    float oc[8][4];
#pragma unroll
    for (int i = 0; i < 8; i++)
#pragma unroll
        for (int e = 0; e < 4; e++) oc[i][e] = 0.f;
    float l_i[2] = {0.f, 0.f};
    int qr = lane >> 2, lm4 = lane & 3;

    for (int kt = 0; kt < 16; kt++) {
        CP_WAIT0();
        __syncthreads();
        if (kt + 1 < 16) FISSUE(kt + 1);

        uint32_t bufb = sm + FBUF0 + (kt & 1) * FBUFSZ;
        uint32_t kb_base = bufb + l16 * 336 + lh * 16;
        uint32_t vh_base = bufb + FV_OFF + l16 * 144 + lh * 16;
        uint32_t vl_base = bufb + FVL_OFF + l16 * 144 + lh * 16;
        const float* kbs = (const float*)(fsm + FBUF0 + (kt & 1) * FBUFSZ + FKB_OFF);

        // ---- S = Q_ext . K_ext^T : phase-major, 8-wide independent sweeps ----
        float sc[8][4];
#pragma unroll
        for (int i = 0; i < 8; i++)
#pragma unroll
            for (int e = 0; e < 4; e++) sc[i][e] = 0.f;

#pragma unroll
        for (int ks = 0; ks < 5; ks++) {
            uint32_t ah[4], al[4];
            LDMX4(ah[0], ah[1], ah[2], ah[3], qa_base + ks * 32);
            LDMX4(al[0], al[1], al[2], al[3], qa_base + 160 + ks * 32);
            uint32_t bh4[4][4], bl4[4][4];
#pragma unroll
            for (int nfp = 0; nfp < 4; nfp++) {
                LDMX4(bh4[nfp][0], bh4[nfp][1], bh4[nfp][2], bh4[nfp][3],
                      kb_base + nfp * 5376 + ks * 32);
                LDMX4(bl4[nfp][0], bl4[nfp][1], bl4[nfp][2], bl4[nfp][3],
                      kb_base + nfp * 5376 + 160 + ks * 32);
            }
#pragma unroll
            for (int nfp = 0; nfp < 4; nfp++) {
                uint32_t be[2] = { bh4[nfp][0], bh4[nfp][2] };
                uint32_t bo[2] = { bh4[nfp][1], bh4[nfp][3] };
                mma16816(sc[2 * nfp],     ah, be);
                mma16816(sc[2 * nfp + 1], ah, bo);
            }
#pragma unroll
            for (int nfp = 0; nfp < 4; nfp++) {
                uint32_t be[2] = { bh4[nfp][0], bh4[nfp][2] };
                uint32_t bo[2] = { bh4[nfp][1], bh4[nfp][3] };
                mma16816(sc[2 * nfp],     al, be);
                mma16816(sc[2 * nfp + 1], al, bo);
            }
#pragma unroll
            for (int nfp = 0; nfp < 4; nfp++) {
                uint32_t be[2] = { bl4[nfp][0], bl4[nfp][2] };
                uint32_t bo[2] = { bl4[nfp][1], bl4[nfp][3] };
                mma16816(sc[2 * nfp],     ah, be);
                mma16816(sc[2 * nfp + 1], ah, bo);
            }
        }

        // ---- bias + exp + pack P (hi and lo) in-register ----
        uint32_t ph_[8][2], pl_[8][2];
#pragma unroll
        for (int nf = 0; nf < 8; nf++) {
            int k0 = nf * 8 + 2 * lm4;
            float kb0 = kbs[k0], kb1 = kbs[k0 + 1];
            float e0 = __expf(sc[nf][0] + kb0);
            float e1 = __expf(sc[nf][1] + kb1);
            float e2 = __expf(sc[nf][2] + kb0);
            float e3 = __expf(sc[nf][3] + kb1);
            l_i[0] += e0 + e1;
            l_i[1] += e2 + e3;
            __nv_bfloat16 h0, l0, h1, l1, h2, l2, h3, l3;
            bf16split(e0, h0, l0); bf16split(e1, h1, l1);
            bf16split(e2, h2, l2); bf16split(e3, h3, l3);
            ph_[nf][0] = pk2(h0, h1); ph_[nf][1] = pk2(h2, h3);
            pl_[nf][0] = pk2(l0, l1); pl_[nf][1] = pk2(l2, l3);
        }

        // ---- O += Ph.Vh + Pl.Vh + Ph.Vl : 3 phases ----
#pragma unroll
        for (int t = 0; t < 4; t++) {
            uint32_t aph[4] = { ph_[2 * t][0], ph_[2 * t][1],
                                ph_[2 * t + 1][0], ph_[2 * t + 1][1] };
            uint32_t apl[4] = { pl_[2 * t][0], pl_[2 * t][1],
                                pl_[2 * t + 1][0], pl_[2 * t + 1][1] };
            uint32_t vh4[4][4], vl4[4][4];
#pragma unroll
            for (int nfvp = 0; nfvp < 4; nfvp++) {
                LDMX4(vh4[nfvp][0], vh4[nfvp][1], vh4[nfvp][2], vh4[nfvp][3],
                      vh_base + nfvp * 2304 + t * 32);
                LDMX4(vl4[nfvp][0], vl4[nfvp][1], vl4[nfvp][2], vl4[nfvp][3],
                      vl_base + nfvp * 2304 + t * 32);
            }
#pragma unroll
            for (int nfvp = 0; nfvp < 4; nfvp++) {
                uint32_t ve[2] = { vh4[nfvp][0], vh4[nfvp][2] };
                uint32_t vo[2] = { vh4[nfvp][1], vh4[nfvp][3] };
                mma16816(oc[2 * nfvp],     aph, ve);
                mma16816(oc[2 * nfvp + 1], aph, vo);
            }
#pragma unroll
            for (int nfvp = 0; nfvp < 4; nfvp++) {
                uint32_t ve[2] = { vh4[nfvp][0], vh4[nfvp][2] };
                uint32_t vo[2] = { vh4[nfvp][1], vh4[nfvp][3] };
                mma16816(oc[2 * nfvp],     apl, ve);
                mma16816(oc[2 * nfvp + 1], apl, vo);
            }
#pragma unroll
            for (int nfvp = 0; nfvp < 4; nfvp++) {
                uint32_t ve[2] = { vl4[nfvp][0], vl4[nfvp][2] };
                uint32_t vo[2] = { vl4[nfvp][1], vl4[nfvp][3] };
                mma16816(oc[2 * nfvp],     aph, ve);
                mma16816(oc[2 * nfvp + 1], aph, vo);
            }
        }
    }
#undef FISSUE

    l_i[0] += __shfl_xor_sync(0xffffffffu, l_i[0], 1);
    l_i[0] += __shfl_xor_sync(0xffffffffu, l_i[0], 2);
    l_i[1] += __shfl_xor_sync(0xffffffffu, l_i[1], 1);
    l_i[1] += __shfl_xor_sync(0xffffffffu, l_i[1], 2);
    float inv0 = 1.0f / l_i[0], inv1 = 1.0f / l_i[1];

    int b = bh >> 3, h = bh & 7;
    int l0r = i0 + wid * 16 + qr;
    size_t base0 = (size_t)(b * NL + l0r) * GKS;
    size_t base1 = (size_t)(b * NL + l0r + 8) * GKS;
#pragma unroll
    for (int nfv = 0; nfv < 8; nfv++) {
        int col = h * 64 + nfv * 8 + 2 * lm4;
        float v0 = oc[nfv][0] * inv0, v1 = oc[nfv][1] * inv0;
        float w0 = oc[nfv][2] * inv1, w1 = oc[nfv][3] * inv1;
        __nv_bfloat16 vh0, vlo0, vh1, vlo1, wh0, wlo0, wh1, wlo1;
        bf16split(v0, vh0, vlo0); bf16split(v1, vh1, vlo1);
        bf16split(w0, wh0, wlo0); bf16split(w1, wh1, wlo1);
        *(uint32_t*)&g_Oc[base0 + col]       = pk2(vh0, vh1);
        *(uint32_t*)&g_Oc[base0 + 512 + col] = pk2(vlo0, vlo1);
        *(uint32_t*)&g_Oc[base1 + col]       = pk2(wh0, wh1);
        *(uint32_t*)&g_Oc[base1 + 512 + col] = pk2(wlo0, wlo1);
    }
}

// ---------------- launch -----------------------------------------------------
extern "C" void kernel_launch(void* const* d_in, const int* in_sizes, int n_in,
                              void* d_out, int out_size) {
    const float* features = (const float*)d_in[0];
    const float* ln_g = (const float*)d_in[2];
    const float* ln_b = (const float*)d_in[3];
    const float* wq  = (const float*)d_in[4];  const float* bq  = (const float*)d_in[5];
    const float* wk  = (const float*)d_in[6];  const float* bk  = (const float*)d_in[7];
    const float* wv  = (const float*)d_in[8];  const float* bv  = (const float*)d_in[9];
    const float* wqp = (const float*)d_in[10]; const float* bqp = (const float*)d_in[11];
    const float* wkp = (const float*)d_in[12]; const float* bkp = (const float*)d_in[13];
    const float* wo  = (const float*)d_in[16]; const float* bo  = (const float*)d_in[17];
    const float* pscale = (const float*)d_in[18];
    float* out = (float*)d_out;

    const int SMEM0 = (128 + 128) * 272 * 2;   // 139264
    const int SMEM1 = (64 + 128) * 272 * 2;    // 104448
    cudaFuncSetAttribute(gemm_cp<0, 128, 128>, cudaFuncAttributeMaxDynamicSharedMemorySize, SMEM0);
    cudaFuncSetAttribute(gemm_cp<1, 64, 128>,  cudaFuncAttributeMaxDynamicSharedMemorySize, SMEM1);
    cudaFuncSetAttribute(flash_tc, cudaFuncAttributeMaxDynamicSharedMemorySize, FLASH_SMEM);

    pack_w<<<dim3(16, 72), 256>>>(wq, wk, wv, wqp, wkp, wo, pscale);
    pack_bias<<<7, 256>>>(bq, bk, bv, bqp, bkp, pscale);
    ln_kernel<<<NM, 256>>>(features, ln_g, ln_b);
    gemm_cp<0, 128, 128><<<dim3(NCOLP / 128, NM / 128), 256, SMEM0>>>(nullptr, nullptr);
    kbias_kernel<<<(NBH * NL + 255) / 256, 256>>>(pscale);
    flash_tc<<<dim3(NL / 64, NBH), 128, FLASH_SMEM>>>();
    gemm_cp<1, 64, 128><<<dim3(NC / 128, NM / 64), 256, SMEM1>>>(bo, out);
}

// round 17
// speedup vs baseline: 1.1094x; 1.1094x over previous
#include <cuda_runtime.h>
#include <cuda_bf16.h>
#include <cstdint>
#include <stdint.h>

// ---------------- problem constants -----------------------------------------
#define NL   1024
#define NC   512
#define NCOL 1728
#define NM   2048
#define NBH  16
#define GK   1536        // logical split-concat K' = 3*512
#define GKS  1024        // physical storage: [hi(512) | lo(512)]

// ---------------- scratch ----------------------------------------------------
__device__ float g_Kp[NBH * NL * 12];
__device__ float g_kb[NBH * NL];
__device__ float g_bias[NCOL];
__device__ __nv_bfloat16 g_xc[NM * GKS];         // LN(x) [hi|lo]
__device__ __nv_bfloat16 g_Wc[NCOL * GKS];       // packed W^T [hi|lo]
__device__ __nv_bfloat16 g_Oc[NM * GKS];         // attn out [hi|lo]
__device__ __nv_bfloat16 g_WoC[NC * GKS];        // wo^T [hi|lo]
__device__ __nv_bfloat16 g_Qc[NBH * NL * 160];   // q_ext bf16 [hi|lo]; pads stay 0
__device__ __nv_bfloat16 g_Kc[NBH * NL * 160];
__device__ __nv_bfloat16 g_VhT[NBH * 64 * NL];   // V hi, transposed [bh*64+d][l]
__device__ __nv_bfloat16 g_VlT[NBH * 64 * NL];   // V lo, transposed

__device__ __forceinline__ void bf16split(float v, __nv_bfloat16& hi, __nv_bfloat16& lo) {
    hi = __float2bfloat16(v);
    lo = __float2bfloat16(v - __bfloat162float(hi));
}
__device__ __forceinline__ uint32_t pk2(__nv_bfloat16 a, __nv_bfloat16 b) {
    return (uint32_t)__bfloat16_as_ushort(a) | ((uint32_t)__bfloat16_as_ushort(b) << 16);
}
__device__ __forceinline__ uint32_t smem_u32(const void* p) {
    uint32_t a;
    asm("{ .reg .u64 t; cvta.to.shared.u64 t, %1; cvt.u32.u64 %0, t; }" : "=r"(a) : "l"(p));
    return a;
}
__device__ __forceinline__ void mma16816(float* c, const uint32_t* a, const uint32_t* b) {
    asm volatile("mma.sync.aligned.m16n8k16.row.col.f32.bf16.bf16.f32 "
                 "{%0,%1,%2,%3}, {%4,%5,%6,%7}, {%8,%9}, {%0,%1,%2,%3};"
                 : "+f"(c[0]), "+f"(c[1]), "+f"(c[2]), "+f"(c[3])
                 : "r"(a[0]), "r"(a[1]), "r"(a[2]), "r"(a[3]), "r"(b[0]), "r"(b[1]));
}
__device__ __forceinline__ void cpa16(uint32_t dst, const void* src) {
    asm volatile("cp.async.ca.shared.global [%0], [%1], 16;" :: "r"(dst), "l"(src));
}
#define CP_COMMIT() asm volatile("cp.async.commit_group;")
#define CP_WAIT0()  asm volatile("cp.async.wait_group 0;")
#define LDMX4(r0, r1, r2, r3, addr)                                                   \
    asm volatile("ldmatrix.sync.aligned.m8n8.x4.shared.b16 {%0,%1,%2,%3}, [%4];"      \
                 : "=r"(r0), "=r"(r1), "=r"(r2), "=r"(r3) : "r"(addr))

// ---------------- 1) pack weights via 32x32 smem transpose -------------------
__global__ void __launch_bounds__(256) pack_w(const float* __restrict__ wq,
                                              const float* __restrict__ wk,
                                              const float* __restrict__ wv,
                                              const float* __restrict__ wqp,
                                              const float* __restrict__ wkp,
                                              const float* __restrict__ wo,
                                              const float* __restrict__ pscale) {
    __shared__ float smt[32][33];
    int tx = threadIdx.x & 31, ty = threadIdx.x >> 5;
    int k0 = blockIdx.x * 32;
    int nt = blockIdx.y;
    if (nt < 54) {
        int n0 = nt * 32;
        const float* src; int ld, col;
        if (n0 < 512)       { src = wq;  ld = 512; col = n0; }
        else if (n0 < 1024) { src = wk;  ld = 512; col = n0 - 512; }
        else if (n0 < 1536) { src = wv;  ld = 512; col = n0 - 1024; }
        else if (n0 < 1632) { src = wqp; ld = 96;  col = n0 - 1536; }
        else                { src = wkp; ld = 96;  col = n0 - 1632; }
#pragma unroll
        for (int i = 0; i < 4; i++) {
            int kr = ty + i * 8;
            smt[kr][tx] = src[(size_t)(k0 + kr) * ld + col + tx];
        }
        __syncthreads();
#pragma unroll
        for (int i = 0; i < 4; i++) {
            int n = n0 + ty + i * 8, k = k0 + tx;
            float v = smt[tx][ty + i * 8];
            if (n < 512) v *= 0.125f;
            else if (n >= 1536 && n < 1632) v *= 2.0f * pscale[(n - 1536) / 12];
            __nv_bfloat16 hi, lo; bf16split(v, hi, lo);
            g_Wc[(size_t)n * GKS + k]       = hi;
            g_Wc[(size_t)n * GKS + 512 + k] = lo;
        }
    } else {
        int n0 = (nt - 54) * 32;
#pragma unroll
        for (int i = 0; i < 4; i++) {
            int kr = ty + i * 8;
            smt[kr][tx] = wo[(size_t)(k0 + kr) * 512 + n0 + tx];
        }
        __syncthreads();
#pragma unroll
        for (int i = 0; i < 4; i++) {
            int n = n0 + ty + i * 8, k = k0 + tx;
            __nv_bfloat16 hi, lo; bf16split(smt[tx][ty + i * 8], hi, lo);
            g_WoC[(size_t)n * GKS + k]       = hi;
            g_WoC[(size_t)n * GKS + 512 + k] = lo;
        }
    }
}

__global__ void pack_bias(const float* __restrict__ bq, const float* __restrict__ bk,
                          const float* __restrict__ bv, const float* __restrict__ bqp,
                          const float* __restrict__ bkp, const float* __restrict__ pscale) {
    int n = blockIdx.x * 256 + threadIdx.x;
    if (n >= NCOL) return;
    float bb;
    if (n < 512)        bb = bq[n] * 0.125f;
    else if (n < 1024)  bb = bk[n - 512];
    else if (n < 1536)  bb = bv[n - 1024];
    else if (n < 1632) { int c = n - 1536; bb = bqp[c] * 2.0f * pscale[c / 12]; }
    else               { int c = n - 1632; bb = bkp[c]; }
    g_bias[n] = bb;
}

// ---------------- 2) LayerNorm -> [hi|lo] bf16 -------------------------------
__global__ void ln_kernel(const float* __restrict__ f, const float* __restrict__ g,
                          const float* __restrict__ bb) {
    int row = blockIdx.x, t = threadIdx.x;
    const float* xr = f + (size_t)row * NC;
    float v0 = xr[t], v1 = xr[t + 256];
    float s = v0 + v1, s2 = v0 * v0 + v1 * v1;
#pragma unroll
    for (int o = 16; o > 0; o >>= 1) {
        s  += __shfl_xor_sync(0xffffffffu, s, o);
        s2 += __shfl_xor_sync(0xffffffffu, s2, o);
    }
    __shared__ float sh[16];
    if ((t & 31) == 0) { sh[t >> 5] = s; sh[8 + (t >> 5)] = s2; }
    __syncthreads();
    float ts = 0.f, ts2 = 0.f;
#pragma unroll
    for (int i = 0; i < 8; i++) { ts += sh[i]; ts2 += sh[8 + i]; }
    float mu   = ts * (1.0f / NC);
    float var  = ts2 * (1.0f / NC) - mu * mu;
    float rstd = rsqrtf(var + 1e-5f);
    float x0 = (v0 - mu) * rstd * g[t] + bb[t];
    float x1 = (v1 - mu) * rstd * g[t + 256] + bb[t + 256];
    size_t base = (size_t)row * GKS;
    __nv_bfloat16 h0, l0, h1, l1;
    bf16split(x0, h0, l0); bf16split(x1, h1, l1);
    g_xc[base + t]       = h0;  g_xc[base + t + 256]       = h1;
    g_xc[base + 512 + t] = l0;  g_xc[base + 512 + t + 256] = l1;
}

// ---------------- 3) GEMM: ldmatrix + BK=128, 2-stage cp.async ---------------
// Logical K'=1536 over 2-plane storage:
//   A plane map (x/O = [hi,lo,hi]):  ka = k0>=1024 ? k0-1024 : k0
//   B plane map (W   = [hi,hi,lo]):  kb = k0>=512  ? k0-512  : k0
template <int MODE, int MT, int NT>
__global__ void __launch_bounds__(256) gemm_cp(const float* __restrict__ bias2,
                                               float* __restrict__ outp) {
    constexpr int STAGE = (MT + NT) * 272;
    constexpr int MFRAG = MT / 32;
    constexpr int NWN   = NT / 4;
    constexpr int NFRAG = NWN / 8;
    constexpr int NFP   = NWN / 16;
    constexpr int ITERS = (MT + NT) * 16 / 256;
    extern __shared__ char gsm[];
    uint32_t smBase = smem_u32(gsm);
    int tid = threadIdx.x, lane = tid & 31, wid = tid >> 5;
    int wm = wid & 1, wn = wid >> 1;
    int l16 = lane & 15, lh = lane >> 4;
    int m0 = blockIdx.y * MT, n0 = blockIdx.x * NT;
    const __nv_bfloat16* Ap = (MODE == 0 ? g_xc : g_Oc) + (size_t)m0 * GKS;
    const __nv_bfloat16* Bp = (MODE == 0 ? g_Wc : g_WoC) + (size_t)n0 * GKS;

#define GEMM_ISSUE(S) do {                                                         \
    int st_ = (S) & 1; int k0_ = (S) * 128;                                        \
    int ka_ = (k0_ >= 1024) ? (k0_ - 1024) : k0_;                                  \
    int kb_ = (k0_ >= 512)  ? (k0_ - 512)  : k0_;                                  \
    uint32_t base_ = smBase + st_ * STAGE;                                         \
    _Pragma("unroll")                                                              \
    for (int i_ = 0; i_ < ITERS; i_++) {                                           \
        int idx_ = tid + i_ * 256;                                                 \
        int row_ = idx_ >> 4, ch_ = idx_ & 15;                                     \
        const __nv_bfloat16* src_ = (row_ < MT)                                    \
            ? Ap + (size_t)row_ * GKS + ka_ + ch_ * 8                              \
            : Bp + (size_t)(row_ - MT) * GKS + kb_ + ch_ * 8;                      \
        cpa16(base_ + row_ * 272 + ch_ * 16, src_);                                \
    }                                                                              \
    CP_COMMIT();                                                                   \
} while (0)

    GEMM_ISSUE(0);

    float c[MFRAG][NFRAG][4];
#pragma unroll
    for (int i = 0; i < MFRAG; i++)
#pragma unroll
        for (int j = 0; j < NFRAG; j++)
#pragma unroll
            for (int e = 0; e < 4; e++) c[i][j][e] = 0.f;

    const int NS = GK / 128;   // 12
    for (int s = 0; s < NS; s++) {
        CP_WAIT0();
        __syncthreads();
        if (s + 1 < NS) GEMM_ISSUE(s + 1);
        uint32_t aB = smBase + (s & 1) * STAGE;
        uint32_t a_ad = aB + (wm * (MT / 2) + l16) * 272 + lh * 16;
        uint32_t b_ad = aB + MT * 272 + (wn * NWN + l16) * 272 + lh * 16;
#pragma unroll
        for (int ks = 0; ks < 8; ks++) {
            uint32_t a[MFRAG][4], bb[NFP][4];
#pragma unroll
            for (int mf = 0; mf < MFRAG; mf++)
                LDMX4(a[mf][0], a[mf][1], a[mf][2], a[mf][3], a_ad + mf * 4352 + ks * 32);
#pragma unroll
            for (int nfp = 0; nfp < NFP; nfp++)
                LDMX4(bb[nfp][0], bb[nfp][1], bb[nfp][2], bb[nfp][3], b_ad + nfp * 4352 + ks * 32);
#pragma unroll
            for (int mf = 0; mf < MFRAG; mf++)
#pragma unroll
                for (int nfp = 0; nfp < NFP; nfp++) {
                    uint32_t be[2] = { bb[nfp][0], bb[nfp][2] };
                    uint32_t bo[2] = { bb[nfp][1], bb[nfp][3] };
                    mma16816(c[mf][2 * nfp],     a[mf], be);
                    mma16816(c[mf][2 * nfp + 1], a[mf], bo);
                }
        }
        __syncthreads();
    }
#undef GEMM_ISSUE

    // epilogue
#pragma unroll
    for (int mf = 0; mf < MFRAG; mf++) {
#pragma unroll
        for (int nf = 0; nf < NFRAG; nf++) {
#pragma unroll
            for (int ep = 0; ep < 2; ep++) {
                int m = m0 + wm * (MT / 2) + mf * 16 + (lane >> 2) + ep * 8;
                int n = n0 + wn * NWN + nf * 8 + (lane & 3) * 2;
                float v0 = c[mf][nf][ep * 2 + 0];
                float v1 = c[mf][nf][ep * 2 + 1];
                if (MODE == 0) {
                    v0 += g_bias[n]; v1 += g_bias[n + 1];
                    int b = m >> 10, l = m & 1023;
                    __nv_bfloat16 h0, lo0, h1, lo1;
                    bf16split(v0, h0, lo0); bf16split(v1, h1, lo1);
                    if (n < 512) {
                        int h = n >> 6, d = n & 63;
                        size_t row = (size_t)((b * 8 + h) * NL + l) * 160;
                        *(uint32_t*)&g_Qc[row + d]      = pk2(h0, h1);
                        *(uint32_t*)&g_Qc[row + 80 + d] = pk2(lo0, lo1);
                    } else if (n < 1024) {
                        int n2 = n - 512; int h = n2 >> 6, d = n2 & 63;
                        size_t row = (size_t)((b * 8 + h) * NL + l) * 160;
                        *(uint32_t*)&g_Kc[row + d]      = pk2(h0, h1);
                        *(uint32_t*)&g_Kc[row + 80 + d] = pk2(lo0, lo1);
                    } else if (n < 1536) {
                        int n2 = n - 1024; int h = n2 >> 6, d = n2 & 63;
                        size_t vb = (size_t)((b * 8 + h) * 64 + d) * NL + l;
                        g_VhT[vb]      = h0;
                        g_VhT[vb + NL] = h1;
                        g_VlT[vb]      = lo0;
                        g_VlT[vb + NL] = lo1;
                    } else if (n < 1632) {
                        int cc = n - 1536; int h = cc / 12, r = cc - h * 12;
                        size_t row = (size_t)((b * 8 + h) * NL + l) * 160;
                        *(uint32_t*)&g_Qc[row + 64 + r]  = pk2(h0, h1);
                        *(uint32_t*)&g_Qc[row + 144 + r] = pk2(lo0, lo1);
                    } else {
                        int cc = n - 1632; int h = cc / 12, r = cc - h * 12;
                        size_t row = (size_t)((b * 8 + h) * NL + l);
                        *(uint32_t*)&g_Kc[row * 160 + 64 + r]  = pk2(h0, h1);
                        *(uint32_t*)&g_Kc[row * 160 + 144 + r] = pk2(lo0, lo1);
                        *(float2*)&g_Kp[row * 12 + r] = make_float2(v0, v1);
                    }
                } else {
                    *(float2*)&outp[(size_t)m * NC + n] =
                        make_float2(v0 + bias2[n], v1 + bias2[n + 1]);
                }
            }
        }
    }
}

// ---------------- 4) key bias -----------------------------------------------
__global__ void kbias_kernel(const float* __restrict__ pscale) {
    int row = blockIdx.x * blockDim.x + threadIdx.x;
    if (row >= NBH * NL) return;
    int h = (row >> 10) & 7;
    float s = 0.f;
#pragma unroll
    for (int r = 0; r < 12; r++) { float v = g_Kp[row * 12 + r]; s += v * v; }
    g_kb[row] = -pscale[h] * s;
}

// ---------------- 5) flash attention: S 3-phase, PV 3-phase ------------------
#define FBUF0 21504
#define FBUFSZ 40192
#define FV_OFF 21504
#define FVL_OFF 30720
#define FKB_OFF 39936
#define FLASH_SMEM (21504 + 2 * FBUFSZ)

__global__ void __launch_bounds__(128) flash_tc() {
    extern __shared__ char fsm[];
    __nv_bfloat16* Qs = (__nv_bfloat16*)fsm;
    uint32_t sm = smem_u32(fsm);

    int tid = threadIdx.x, lane = tid & 31, wid = tid >> 5;
    int l16 = lane & 15, lh = lane >> 4;
    int bh = blockIdx.y, i0 = blockIdx.x << 6;

    const __nv_bfloat16* Qg = g_Qc + (size_t)(bh * NL + i0) * 160;
    const __nv_bfloat16* Kg0 = g_Kc + (size_t)(bh * NL) * 160;
    const __nv_bfloat16* VhG = g_VhT + (size_t)(bh * 64) * NL;
    const __nv_bfloat16* VlG = g_VlT + (size_t)(bh * 64) * NL;
    const float* kbG = g_kb + bh * NL;

#define FISSUE(KT) do {                                                              \
    int j0_ = (KT) << 6;                                                             \
    uint32_t bufb_ = sm + FBUF0 + ((KT) & 1) * FBUFSZ;                               \
    const __nv_bfloat16* Kg_ = Kg0 + (size_t)j0_ * 160;                              \
    _Pragma("unroll")                                                                \
    for (int i_ = 0; i_ < 10; i_++) {                                                \
        int idx_ = tid + i_ * 128;                                                   \
        int row_ = idx_ / 20, ch_ = idx_ % 20;                                       \
        cpa16(bufb_ + row_ * 336 + ch_ * 16, Kg_ + row_ * 160 + ch_ * 8);            \
    }                                                                                \
    _Pragma("unroll")                                                                \
    for (int i_ = 0; i_ < 4; i_++) {                                                 \
        int idx_ = tid + i_ * 128;                                                   \
        int d_ = idx_ >> 3, ch_ = idx_ & 7;                                          \
        cpa16(bufb_ + FV_OFF + d_ * 144 + ch_ * 16, VhG + (size_t)d_ * NL + j0_ + ch_ * 8); \
        cpa16(bufb_ + FVL_OFF + d_ * 144 + ch_ * 16, VlG + (size_t)d_ * NL + j0_ + ch_ * 8); \
    }                                                                                \
    if (tid < 16) cpa16(bufb_ + FKB_OFF + tid * 16, kbG + j0_ + tid * 4);            \
    CP_COMMIT();                                                                     \
} while (0)

    FISSUE(0);

    for (int idx = tid; idx < 64 * 20; idx += 128) {
        int row = idx / 20, ch = idx % 20;
        *(uint4*)&Qs[row * 168 + ch * 8] = *(const uint4*)(Qg + row * 160 + ch * 8);
    }
    uint32_t qa_base = sm + (wid * 16 + l16) * 336 + lh * 16;

    float oc[8][4];
#pragma unroll
    for (int i = 0; i < 8; i++)
#pragma unroll
        for (int e = 0; e < 4; e++) oc[i][e] = 0.f;
    float l_i[2] = {0.f, 0.f};
    int qr = lane >> 2, lm4 = lane & 3;

    for (int kt = 0; kt < 16; kt++) {
        CP_WAIT0();
        __syncthreads();
        if (kt + 1 < 16) FISSUE(kt + 1);

        uint32_t bufb = sm + FBUF0 + (kt & 1) * FBUFSZ;
        uint32_t kb_base = bufb + l16 * 336 + lh * 16;
        uint32_t vh_base = bufb + FV_OFF + l16 * 144 + lh * 16;
        uint32_t vl_base = bufb + FVL_OFF + l16 * 144 + lh * 16;
        const float* kbs = (const float*)(fsm + FBUF0 + (kt & 1) * FBUFSZ + FKB_OFF);

        // ---- S = Q_ext . K_ext^T : phase-major, 8-wide independent sweeps ----
        float sc[8][4];
#pragma unroll
        for (int i = 0; i < 8; i++)
#pragma unroll
            for (int e = 0; e < 4; e++) sc[i][e] = 0.f;

#pragma unroll
        for (int ks = 0; ks < 5; ks++) {
            uint32_t ah[4], al[4];
            LDMX4(ah[0], ah[1], ah[2], ah[3], qa_base + ks * 32);
            LDMX4(al[0], al[1], al[2], al[3], qa_base + 160 + ks * 32);
            uint32_t bh4[4][4], bl4[4][4];
#pragma unroll
            for (int nfp = 0; nfp < 4; nfp++) {
                LDMX4(bh4[nfp][0], bh4[nfp][1], bh4[nfp][2], bh4[nfp][3],
                      kb_base + nfp * 5376 + ks * 32);
                LDMX4(bl4[nfp][0], bl4[nfp][1], bl4[nfp][2], bl4[nfp][3],
                      kb_base + nfp * 5376 + 160 + ks * 32);
            }
#pragma unroll
            for (int nfp = 0; nfp < 4; nfp++) {
                uint32_t be[2] = { bh4[nfp][0], bh4[nfp][2] };
                uint32_t bo[2] = { bh4[nfp][1], bh4[nfp][3] };
                mma16816(sc[2 * nfp],     ah, be);
                mma16816(sc[2 * nfp + 1], ah, bo);
            }
#pragma unroll
            for (int nfp = 0; nfp < 4; nfp++) {
                uint32_t be[2] = { bh4[nfp][0], bh4[nfp][2] };
                uint32_t bo[2] = { bh4[nfp][1], bh4[nfp][3] };
                mma16816(sc[2 * nfp],     al, be);
                mma16816(sc[2 * nfp + 1], al, bo);
            }
#pragma unroll
            for (int nfp = 0; nfp < 4; nfp++) {
                uint32_t be[2] = { bl4[nfp][0], bl4[nfp][2] };
                uint32_t bo[2] = { bl4[nfp][1], bl4[nfp][3] };
                mma16816(sc[2 * nfp],     ah, be);
                mma16816(sc[2 * nfp + 1], ah, bo);
            }
        }

        // ---- bias + exp + pack P (hi and lo) in-register ----
        uint32_t ph_[8][2], pl_[8][2];
#pragma unroll
        for (int nf = 0; nf < 8; nf++) {
            int k0 = nf * 8 + 2 * lm4;
            float kb0 = kbs[k0], kb1 = kbs[k0 + 1];
            float e0 = __expf(sc[nf][0] + kb0);
            float e1 = __expf(sc[nf][1] + kb1);
            float e2 = __expf(sc[nf][2] + kb0);
            float e3 = __expf(sc[nf][3] + kb1);
            l_i[0] += e0 + e1;
            l_i[1] += e2 + e3;
            __nv_bfloat16 h0, l0, h1, l1, h2, l2, h3, l3;
            bf16split(e0, h0, l0); bf16split(e1, h1, l1);
            bf16split(e2, h2, l2); bf16split(e3, h3, l3);
            ph_[nf][0] = pk2(h0, h1); ph_[nf][1] = pk2(h2, h3);
            pl_[nf][0] = pk2(l0, l1); pl_[nf][1] = pk2(l2, l3);
        }

        // ---- O += Ph.Vh + Pl.Vh + Ph.Vl : 3 phases ----
#pragma unroll
        for (int t = 0; t < 4; t++) {
            uint32_t aph[4] = { ph_[2 * t][0], ph_[2 * t][1],
                                ph_[2 * t + 1][0], ph_[2 * t + 1][1] };
            uint32_t apl[4] = { pl_[2 * t][0], pl_[2 * t][1],
                                pl_[2 * t + 1][0], pl_[2 * t + 1][1] };
            uint32_t vh4[4][4], vl4[4][4];
#pragma unroll
            for (int nfvp = 0; nfvp < 4; nfvp++) {
                LDMX4(vh4[nfvp][0], vh4[nfvp][1], vh4[nfvp][2], vh4[nfvp][3],
                      vh_base + nfvp * 2304 + t * 32);
                LDMX4(vl4[nfvp][0], vl4[nfvp][1], vl4[nfvp][2], vl4[nfvp][3],
                      vl_base + nfvp * 2304 + t * 32);
            }
#pragma unroll
            for (int nfvp = 0; nfvp < 4; nfvp++) {
                uint32_t ve[2] = { vh4[nfvp][0], vh4[nfvp][2] };
                uint32_t vo[2] = { vh4[nfvp][1], vh4[nfvp][3] };
                mma16816(oc[2 * nfvp],     aph, ve);
                mma16816(oc[2 * nfvp + 1], aph, vo);
            }
#pragma unroll
            for (int nfvp = 0; nfvp < 4; nfvp++) {
                uint32_t ve[2] = { vh4[nfvp][0], vh4[nfvp][2] };
                uint32_t vo[2] = { vh4[nfvp][1], vh4[nfvp][3] };
                mma16816(oc[2 * nfvp],     apl, ve);
                mma16816(oc[2 * nfvp + 1], apl, vo);
            }
#pragma unroll
            for (int nfvp = 0; nfvp < 4; nfvp++) {
                uint32_t ve[2] = { vl4[nfvp][0], vl4[nfvp][2] };
                uint32_t vo[2] = { vl4[nfvp][1], vl4[nfvp][3] };
                mma16816(oc[2 * nfvp],     aph, ve);
                mma16816(oc[2 * nfvp + 1], aph, vo);
            }
        }
    }
#undef FISSUE

    l_i[0] += __shfl_xor_sync(0xffffffffu, l_i[0], 1);
    l_i[0] += __shfl_xor_sync(0xffffffffu, l_i[0], 2);
    l_i[1] += __shfl_xor_sync(0xffffffffu, l_i[1], 1);
    l_i[1] += __shfl_xor_sync(0xffffffffu, l_i[1], 2);
    float inv0 = 1.0f / l_i[0], inv1 = 1.0f / l_i[1];

    int b = bh >> 3, h = bh & 7;
    int l0r = i0 + wid * 16 + qr;
    size_t base0 = (size_t)(b * NL + l0r) * GKS;
    size_t base1 = (size_t)(b * NL + l0r + 8) * GKS;
#pragma unroll
    for (int nfv = 0; nfv < 8; nfv++) {
        int col = h * 64 + nfv * 8 + 2 * lm4;
        float v0 = oc[nfv][0] * inv0, v1 = oc[nfv][1] * inv0;
        float w0 = oc[nfv][2] * inv1, w1 = oc[nfv][3] * inv1;
        __nv_bfloat16 vh0, vlo0, vh1, vlo1, wh0, wlo0, wh1, wlo1;
        bf16split(v0, vh0, vlo0); bf16split(v1, vh1, vlo1);
        bf16split(w0, wh0, wlo0); bf16split(w1, wh1, wlo1);
        *(uint32_t*)&g_Oc[base0 + col]       = pk2(vh0, vh1);
        *(uint32_t*)&g_Oc[base0 + 512 + col] = pk2(vlo0, vlo1);
        *(uint32_t*)&g_Oc[base1 + col]       = pk2(wh0, wh1);
        *(uint32_t*)&g_Oc[base1 + 512 + col] = pk2(wlo0, wlo1);
    }
}

// ---------------- launch -----------------------------------------------------
extern "C" void kernel_launch(void* const* d_in, const int* in_sizes, int n_in,
                              void* d_out, int out_size) {
    const float* features = (const float*)d_in[0];
    const float* ln_g = (const float*)d_in[2];
    const float* ln_b = (const float*)d_in[3];
    const float* wq  = (const float*)d_in[4];  const float* bq  = (const float*)d_in[5];
    const float* wk  = (const float*)d_in[6];  const float* bk  = (const float*)d_in[7];
    const float* wv  = (const float*)d_in[8];  const float* bv  = (const float*)d_in[9];
    const float* wqp = (const float*)d_in[10]; const float* bqp = (const float*)d_in[11];
    const float* wkp = (const float*)d_in[12]; const float* bkp = (const float*)d_in[13];
    const float* wo  = (const float*)d_in[16]; const float* bo  = (const float*)d_in[17];
    const float* pscale = (const float*)d_in[18];
    float* out = (float*)d_out;

    const int SMEM0 = (128 + 192) * 272 * 2;   // 174080
    const int SMEM1 = (64 + 128) * 272 * 2;    // 104448
    cudaFuncSetAttribute(gemm_cp<0, 128, 192>, cudaFuncAttributeMaxDynamicSharedMemorySize, SMEM0);
    cudaFuncSetAttribute(gemm_cp<1, 64, 128>,  cudaFuncAttributeMaxDynamicSharedMemorySize, SMEM1);
    cudaFuncSetAttribute(flash_tc, cudaFuncAttributeMaxDynamicSharedMemorySize, FLASH_SMEM);

    pack_w<<<dim3(16, 70), 256>>>(wq, wk, wv, wqp, wkp, wo, pscale);
    pack_bias<<<7, 256>>>(bq, bk, bv, bqp, bkp, pscale);
    ln_kernel<<<NM, 256>>>(features, ln_g, ln_b);
    gemm_cp<0, 128, 192><<<dim3(NCOL / 192, NM / 128), 256, SMEM0>>>(nullptr, nullptr);
    kbias_kernel<<<(NBH * NL + 255) / 256, 256>>>(pscale);
    flash_tc<<<dim3(NL / 64, NBH), 128, FLASH_SMEM>>>();
    gemm_cp<1, 64, 128><<<dim3(NC / 128, NM / 64), 256, SMEM1>>>(bo, out);
}